// round 10
// baseline (speedup 1.0000x reference)
#include <cuda_runtime.h>
#include <cuda_bf16.h>
#include <cstdint>
#include <math.h>

#define N_NODES 50000
#define N_EDGES 500000
#define EN      (N_EDGES + N_NODES)   // 550000 incl. self loops
#define D_IN    128
#define D_HID   256
#define BM      128
#define BN      128
#define BK      64
#define N_CTAS  ((N_NODES + BM - 1) / BM)   // 391
#define M_PAD   (N_CTAS * BM)               // 50048

// ---------------- async-copy helpers (portable PTX, sm_80+) -----------------
__device__ __forceinline__ uint32_t smem_to_u32(const void* p) {
    uint32_t a;
    asm("{ .reg .u64 t; cvta.to.shared.u64 t, %1; cvt.u32.u64 %0, t; }" : "=r"(a) : "l"(p));
    return a;
}
__device__ __forceinline__ void cp_async16(uint32_t s, const void* g) {
    asm volatile("cp.async.cg.shared.global [%0], [%1], 16;" :: "r"(s), "l"(g));
}
__device__ __forceinline__ void cp_commit() {
    asm volatile("cp.async.commit_group;" ::: "memory");
}
template <int N>
__device__ __forceinline__ void cp_wait() {
    asm volatile("cp.async.wait_group %0;" :: "n"(N) : "memory");
}
__device__ __forceinline__ void ldsm_x4(uint32_t* r, uint32_t addr) {
    asm volatile("ldmatrix.sync.aligned.m8n8.x4.shared.b16 {%0,%1,%2,%3}, [%4];"
                 : "=r"(r[0]), "=r"(r[1]), "=r"(r[2]), "=r"(r[3]) : "r"(addr));
}
__device__ __forceinline__ void mma_bf16(float* c, const uint32_t* a, const uint32_t* b) {
    asm volatile(
        "mma.sync.aligned.m16n8k16.row.col.f32.bf16.bf16.f32 "
        "{%0,%1,%2,%3}, {%4,%5,%6,%7}, {%8,%9}, {%0,%1,%2,%3};"
        : "+f"(c[0]), "+f"(c[1]), "+f"(c[2]), "+f"(c[3])
        : "r"(a[0]), "r"(a[1]), "r"(a[2]), "r"(a[3]), "r"(b[0]), "r"(b[1]));
}

// ---------------- packed f32x2 helpers --------------------------------------
typedef unsigned long long u64;
__device__ __forceinline__ void unpack_f32x2(u64 v, float& x, float& y) {
    asm("mov.b64 {%0,%1}, %2;" : "=f"(x), "=f"(y) : "l"(v));
}
__device__ __forceinline__ u64 pack_b32x2(uint32_t x, uint32_t y) {
    u64 r; asm("mov.b64 %0, {%1,%2};" : "=l"(r) : "r"(x), "r"(y)); return r;
}
__device__ __forceinline__ void ffma2(u64& d, u64 a, u64 b) {
    asm("fma.rn.f32x2 %0, %1, %2, %0;" : "+l"(d) : "l"(a), "l"(b));
}
// 16B row load directly into two b64 (f32x2 operand) registers
__device__ __forceinline__ void ld_row64(const float* p, u64& a, u64& b) {
    asm volatile("ld.global.nc.v2.b64 {%0,%1}, [%2];" : "=l"(a), "=l"(b) : "l"(p));
}

// ---------------- device scratch (static globals; no allocation) ------------
__device__ int   g_deg[N_NODES];          // zeroed each replay by k_scan
__device__ int   g_row_ptr[N_NODES + 1];
__device__ int   g_pos[N_NODES];
__device__ __align__(8) int2 g_edge[EN];  // zipped {col, norm-bits}
__device__ float g_dinv[N_NODES];
__device__ __align__(16) float g_h[(size_t)N_NODES * D_HID];           // fp32 activations
__device__ __align__(16) __nv_bfloat16 g_ah[(size_t)M_PAD * D_HID];    // split-hi of agg
__device__ __align__(16) __nv_bfloat16 g_al[(size_t)M_PAD * D_HID];    // split-lo of agg
__device__ __align__(16) __nv_bfloat16 g_w1h[D_HID * D_IN];            // W^T [256,128]
__device__ __align__(16) __nv_bfloat16 g_w1l[D_HID * D_IN];
__device__ __align__(16) __nv_bfloat16 g_w2h[D_HID * D_HID];           // W^T [256,256]
__device__ __align__(16) __nv_bfloat16 g_w2l[D_HID * D_HID];
__device__ __align__(16) __nv_bfloat16 g_w3h[D_HID * D_HID];
__device__ __align__(16) __nv_bfloat16 g_w3l[D_HID * D_HID];

// ---------------- CSR + weight split (fused launch 1) ------------------------
#define W1_ELEMS (D_IN * D_HID)
#define W23_ELEMS (D_HID * D_HID)
#define SPLIT_ELEMS (W1_ELEMS + 2 * W23_ELEMS)   // 163840

__device__ __forceinline__ void split_one(const float* W, int K, int idx,
                                          __nv_bfloat16* oh, __nv_bfloat16* ol) {
    int k = idx / D_HID, n = idx % D_HID;
    float v = W[idx];
    __nv_bfloat16 h = __float2bfloat16(v);
    oh[(size_t)n * K + k] = h;
    ol[(size_t)n * K + k] = __float2bfloat16(v - __bfloat162float(h));
}

__global__ void k_count_split(const int* __restrict__ ei,
                              const float* __restrict__ W1,
                              const float* __restrict__ W2,
                              const float* __restrict__ W3) {
    int idx = blockIdx.x * blockDim.x + threadIdx.x;
    if (idx < N_EDGES) {
        atomicAdd(&g_deg[ei[N_EDGES + idx]], 1);
        return;
    }
    int j = idx - N_EDGES;
    if (j < W1_ELEMS) { split_one(W1, D_IN, j, g_w1h, g_w1l); return; }
    j -= W1_ELEMS;
    if (j < W23_ELEMS) { split_one(W2, D_HID, j, g_w2h, g_w2l); return; }
    j -= W23_ELEMS;
    if (j < W23_ELEMS) { split_one(W3, D_HID, j, g_w3h, g_w3l); }
}

// Single-block scan. Degree = g_deg[i] + 1 (self loop). Zeroes g_deg after use.
__global__ void k_scan() {
    __shared__ int s[1024];
    const int t = threadIdx.x;
    const int CH = (N_NODES + 1023) / 1024;
    int start = t * CH;
    int end = start + CH; if (end > N_NODES) end = N_NODES;
    if (start > N_NODES) start = N_NODES;
    int sum = 0;
#pragma unroll 4
    for (int i = start; i < end; i++) sum += g_deg[i] + 1;
    s[t] = sum;
    __syncthreads();
    for (int off = 1; off < 1024; off <<= 1) {
        int v = (t >= off) ? s[t - off] : 0;
        __syncthreads();
        s[t] += v;
        __syncthreads();
    }
    int prefix = (t == 0) ? 0 : s[t - 1];
    for (int i = start; i < end; i++) {
        int d = g_deg[i] + 1;
        g_deg[i] = 0;
        g_row_ptr[i] = prefix;
        g_pos[i] = prefix;
        g_dinv[i] = rsqrtf((float)d);
        prefix += d;
    }
    if (t == 0) g_row_ptr[N_NODES] = s[1023];
}

__global__ void k_fill(const int* __restrict__ ei) {
    int idx = blockIdx.x * blockDim.x + threadIdx.x;
    if (idx < N_EDGES) {
        int s = ei[idx];
        int d = ei[N_EDGES + idx];
        int p = atomicAdd(&g_pos[d], 1);
        g_edge[p] = make_int2(s, __float_as_int(g_dinv[s] * g_dinv[d]));
    } else if (idx < EN) {
        int i = idx - N_EDGES;
        int p = atomicAdd(&g_pos[i], 1);
        float di = g_dinv[i];
        g_edge[p] = make_int2(i, __float_as_int(di * di));
    }
}

// ---------------- aggregation + fp32->bf16 hi/lo split ----------------------
__device__ __forceinline__ void split_store4(__nv_bfloat16* oh, __nv_bfloat16* ol,
                                             size_t off, float4 a) {
    __nv_bfloat16 hx = __float2bfloat16(a.x);
    __nv_bfloat16 hy = __float2bfloat16(a.y);
    __nv_bfloat16 hz = __float2bfloat16(a.z);
    __nv_bfloat16 hw = __float2bfloat16(a.w);
    union { __nv_bfloat162 b[2]; uint2 u; } H, L;
    H.b[0] = __halves2bfloat162(hx, hy);
    H.b[1] = __halves2bfloat162(hz, hw);
    L.b[0] = __halves2bfloat162(__float2bfloat16(a.x - __bfloat162float(hx)),
                                __float2bfloat16(a.y - __bfloat162float(hy)));
    L.b[1] = __halves2bfloat162(__float2bfloat16(a.z - __bfloat162float(hz)),
                                __float2bfloat16(a.w - __bfloat162float(hw)));
    *reinterpret_cast<uint2*>(oh + off) = H.u;
    *reinterpret_cast<uint2*>(ol + off) = L.u;
}

// Warp per node. Edge metadata: one coalesced int2 load per 32 edges + shfl
// (R6/R7-proven). Rows loaded as v2.b64 straight into packed regs; packed
// f32x2 FMAs. 2-way edge unroll with independent accumulator sets.
template <int D>   // 128 or 256
__global__ __launch_bounds__(256) void k_agg_split(
        const float* __restrict__ feat,
        __nv_bfloat16* __restrict__ oh,
        __nv_bfloat16* __restrict__ ol) {
    const int warp = blockIdx.x * (blockDim.x >> 5) + (threadIdx.x >> 5);
    const int lane = threadIdx.x & 31;
    if (warp >= N_NODES) return;
    const int rs = g_row_ptr[warp];
    const int re = g_row_ptr[warp + 1];

    u64 aA0 = 0, aA1 = 0, aA2 = 0, aA3 = 0;
    u64 aB0 = 0, aB1 = 0, aB2 = 0, aB3 = 0;

    for (int j = rs; j < re; j += 32) {
        int m = re - j; if (m > 32) m = 32;
        int cc = 0; uint32_t wb = 0;
        if (lane < m) {
            int2 e = __ldg(&g_edge[j + lane]);
            cc = e.x; wb = (uint32_t)e.y;
        }
        int k = 0;
        for (; k + 1 < m; k += 2) {
            int      c0 = __shfl_sync(0xffffffffu, cc, k);
            uint32_t b0 = __shfl_sync(0xffffffffu, wb, k);
            int      c1 = __shfl_sync(0xffffffffu, cc, k + 1);
            uint32_t b1 = __shfl_sync(0xffffffffu, wb, k + 1);
            u64 w0 = pack_b32x2(b0, b0);
            u64 w1 = pack_b32x2(b1, b1);
            const float* r0 = feat + (size_t)c0 * D + lane * 4;
            const float* r1 = feat + (size_t)c1 * D + lane * 4;
            u64 v0a, v0b, v1a, v1b;
            ld_row64(r0, v0a, v0b);
            ld_row64(r1, v1a, v1b);
            ffma2(aA0, w0, v0a); ffma2(aA1, w0, v0b);
            ffma2(aB0, w1, v1a); ffma2(aB1, w1, v1b);
            if (D == 256) {
                u64 u0a, u0b, u1a, u1b;
                ld_row64(r0 + 128, u0a, u0b);
                ld_row64(r1 + 128, u1a, u1b);
                ffma2(aA2, w0, u0a); ffma2(aA3, w0, u0b);
                ffma2(aB2, w1, u1a); ffma2(aB3, w1, u1b);
            }
        }
        if (k < m) {
            int      c0 = __shfl_sync(0xffffffffu, cc, k);
            uint32_t b0 = __shfl_sync(0xffffffffu, wb, k);
            u64 w0 = pack_b32x2(b0, b0);
            const float* r0 = feat + (size_t)c0 * D + lane * 4;
            u64 v0a, v0b;
            ld_row64(r0, v0a, v0b);
            ffma2(aA0, w0, v0a); ffma2(aA1, w0, v0b);
            if (D == 256) {
                u64 u0a, u0b;
                ld_row64(r0 + 128, u0a, u0b);
                ffma2(aA2, w0, u0a); ffma2(aA3, w0, u0b);
            }
        }
    }

    float4 o0;
    { float x0,y0,x1,y1,x2,y2,x3,y3;
      unpack_f32x2(aA0, x0, y0); unpack_f32x2(aB0, x1, y1);
      unpack_f32x2(aA1, x2, y2); unpack_f32x2(aB1, x3, y3);
      o0.x = x0 + x1; o0.y = y0 + y1; o0.z = x2 + x3; o0.w = y2 + y3; }
    split_store4(oh, ol, (size_t)warp * D + lane * 4, o0);
    if (D == 256) {
        float4 o1;
        float x0,y0,x1,y1,x2,y2,x3,y3;
        unpack_f32x2(aA2, x0, y0); unpack_f32x2(aB2, x1, y1);
        unpack_f32x2(aA3, x2, y2); unpack_f32x2(aB3, x3, y3);
        o1.x = x0 + x1; o1.y = y0 + y1; o1.z = x2 + x3; o1.w = y2 + y3;
        split_store4(oh, ol, (size_t)warp * D + 128 + lane * 4, o1);
    }
}

// ---------------- split-bf16 mma.sync GEMM, merged Ah passes ----------------
// Pass 1 (TP tiles): stage {Ah, Bh, Bl}; compute Ah·Bh + Ah·Bl sharing
// a-fragments. Pass 2 (TP tiles): stage {Al, Bh}; compute Al·Bh.
// 2 stages x 48 KB = 96 KB dynamic SMEM, 2 CTAs/SM. Warps 4(M) x 2(N),
// warp tile 32x64, m16n8k16, SW128 swizzle.
#define STAGE_P 49152                     // stage stride
#define REG_A   0                         // A region within stage
#define REG_B0  16384                     // Bh region
#define REG_B1  32768                     // Bl region (pass 1 only)
#define SMEM_DYN (2 * STAGE_P)            // 98304

template <int KP, bool RELU>
__global__ __launch_bounds__(256, 2) void k_gemm_mma(
    const __nv_bfloat16* __restrict__ Ah, const __nv_bfloat16* __restrict__ Al,
    const __nv_bfloat16* __restrict__ Bh, const __nv_bfloat16* __restrict__ Bl,
    const float* __restrict__ bias, float* __restrict__ C) {
    extern __shared__ __align__(128) char smem[];
    const uint32_t sb = smem_to_u32(smem);
    const int tid  = threadIdx.x;
    const int wid  = tid >> 5;
    const int lane = tid & 31;
    const int wm   = wid >> 1;           // 0..3  (M)
    const int wn   = wid & 1;            // 0..1  (N)
    const int m0   = blockIdx.y * BM;
    const int n0   = blockIdx.x * BN;

    constexpr int TP = KP / BK;          // K chunks (2 or 4)
    constexpr int T  = 2 * TP;           // pass1 tiles then pass2 tiles

    float acc[2][8][4];
#pragma unroll
    for (int i = 0; i < 2; i++)
#pragma unroll
        for (int j = 0; j < 8; j++)
#pragma unroll
            for (int q = 0; q < 4; q++) acc[i][j][q] = 0.f;

    auto load_tile = [&](int buf, int t) {
        const bool p1 = (t < TP);
        const int kc  = (t % TP) * BK;
        const __nv_bfloat16* Ag = p1 ? Ah : Al;
        const uint32_t st = sb + buf * STAGE_P;
#pragma unroll
        for (int i = 0; i < 4; ++i) {
            int c   = tid + i * 256;           // 0..1023
            int row = c >> 3;
            int ch  = c & 7;
            uint32_t sw = row * 128 + ((uint32_t)(ch ^ (row & 7)) << 4);
            const size_t srcA = (size_t)(m0 + row) * KP + kc + ch * 8;
            const size_t srcB = (size_t)(n0 + row) * KP + kc + ch * 8;
            cp_async16(st + REG_A + sw, Ag + srcA);
            cp_async16(st + REG_B0 + sw, Bh + srcB);
            if (p1) cp_async16(st + REG_B1 + sw, Bl + srcB);
        }
    };

    load_tile(0, 0);
    cp_commit();

    for (int t = 0; t < T; ++t) {
        if (t + 1 < T) { load_tile((t + 1) & 1, t + 1); cp_commit(); cp_wait<1>(); }
        else           { cp_wait<0>(); }
        __syncthreads();

        const bool p1 = (t < TP);
        const uint32_t st = sb + (t & 1) * STAGE_P;
#pragma unroll
        for (int ks = 0; ks < 4; ++ks) {
            uint32_t a[2][4];
#pragma unroll
            for (int mi = 0; mi < 2; ++mi) {
                int row = wm * 32 + mi * 16 + (lane & 15);
                uint32_t chunk = (uint32_t)((ks << 1) + (lane >> 4));
                ldsm_x4(a[mi], st + REG_A + row * 128 + ((chunk ^ (row & 7)) << 4));
            }
            uint32_t b[8][2];
            // ---- Bh term
#pragma unroll
            for (int nj = 0; nj < 4; ++nj) {
                int g = lane >> 3;
                int nl = wn * 64 + nj * 16 + ((g >> 1) << 3) + (lane & 7);
                uint32_t chunk = (uint32_t)((ks << 1) + (g & 1));
                uint32_t r4[4];
                ldsm_x4(r4, st + REG_B0 + nl * 128 + ((chunk ^ (nl & 7)) << 4));
                b[nj * 2 + 0][0] = r4[0]; b[nj * 2 + 0][1] = r4[1];
                b[nj * 2 + 1][0] = r4[2]; b[nj * 2 + 1][1] = r4[3];
            }
#pragma unroll
            for (int mi = 0; mi < 2; ++mi)
#pragma unroll
                for (int ni = 0; ni < 8; ++ni)
                    mma_bf16(acc[mi][ni], a[mi], b[ni]);
            // ---- Bl term (pass 1 only), reusing a-fragments
            if (p1) {
#pragma unroll
                for (int nj = 0; nj < 4; ++nj) {
                    int g = lane >> 3;
                    int nl = wn * 64 + nj * 16 + ((g >> 1) << 3) + (lane & 7);
                    uint32_t chunk = (uint32_t)((ks << 1) + (g & 1));
                    uint32_t r4[4];
                    ldsm_x4(r4, st + REG_B1 + nl * 128 + ((chunk ^ (nl & 7)) << 4));
                    b[nj * 2 + 0][0] = r4[0]; b[nj * 2 + 0][1] = r4[1];
                    b[nj * 2 + 1][0] = r4[2]; b[nj * 2 + 1][1] = r4[3];
                }
#pragma unroll
                for (int mi = 0; mi < 2; ++mi)
#pragma unroll
                    for (int ni = 0; ni < 8; ++ni)
                        mma_bf16(acc[mi][ni], a[mi], b[ni]);
            }
        }
        __syncthreads();
    }

    // epilogue: bias + relu, write fp32
    const int lr = lane >> 2;
    const int lc = (lane & 3) * 2;
#pragma unroll
    for (int mi = 0; mi < 2; ++mi) {
        int rb = m0 + wm * 32 + mi * 16 + lr;
#pragma unroll
        for (int half = 0; half < 2; ++half) {
            int r = rb + half * 8;
            if (r < N_NODES) {
                float* crow = C + (size_t)r * D_HID;
#pragma unroll
                for (int ni = 0; ni < 8; ++ni) {
                    int col = n0 + wn * 64 + ni * 8 + lc;
                    float2 bv = *reinterpret_cast<const float2*>(bias + col);
                    float2 o;
                    o.x = acc[mi][ni][half * 2 + 0] + bv.x;
                    o.y = acc[mi][ni][half * 2 + 1] + bv.y;
                    if (RELU) { o.x = fmaxf(o.x, 0.f); o.y = fmaxf(o.y, 0.f); }
                    *reinterpret_cast<float2*>(crow + col) = o;
                }
            }
        }
    }
}

// ---------------- launch ----------------------------------------------------
extern "C" void kernel_launch(void* const* d_in, const int* in_sizes, int n_in,
                              void* d_out, int out_size) {
    const float* x  = (const float*)d_in[0];
    const int*   ei = (const int*)  d_in[1];
    const float* W1 = (const float*)d_in[2];
    const float* b1 = (const float*)d_in[3];
    const float* W2 = (const float*)d_in[4];
    const float* b2 = (const float*)d_in[5];
    const float* W3 = (const float*)d_in[6];
    const float* b3 = (const float*)d_in[7];
    float* out = (float*)d_out;

    cudaFuncSetAttribute(k_gemm_mma<D_IN,  true >, cudaFuncAttributeMaxDynamicSharedMemorySize, SMEM_DYN);
    cudaFuncSetAttribute(k_gemm_mma<D_HID, true >, cudaFuncAttributeMaxDynamicSharedMemorySize, SMEM_DYN);
    cudaFuncSetAttribute(k_gemm_mma<D_HID, false>, cudaFuncAttributeMaxDynamicSharedMemorySize, SMEM_DYN);

    void *p_h, *p_ah, *p_al, *p1h, *p1l, *p2h, *p2l, *p3h, *p3l;
    cudaGetSymbolAddress(&p_h,  g_h);
    cudaGetSymbolAddress(&p_ah, g_ah);
    cudaGetSymbolAddress(&p_al, g_al);
    cudaGetSymbolAddress(&p1h, g_w1h); cudaGetSymbolAddress(&p1l, g_w1l);
    cudaGetSymbolAddress(&p2h, g_w2h); cudaGetSymbolAddress(&p2l, g_w2l);
    cudaGetSymbolAddress(&p3h, g_w3h); cudaGetSymbolAddress(&p3l, g_w3l);
    float* h = (float*)p_h;
    __nv_bfloat16* ah = (__nv_bfloat16*)p_ah;
    __nv_bfloat16* al = (__nv_bfloat16*)p_al;

    // 1) fused degree count + weight split   2) scan (+deg reset)   3) fill
    k_count_split<<<(N_EDGES + SPLIT_ELEMS + 255) / 256, 256>>>(ei, W1, W2, W3);
    k_scan<<<1, 1024>>>();
    k_fill<<<(EN + 255) / 256, 256>>>(ei);

    const int aggBlocks = (N_NODES + 7) / 8;   // 8 warps/block, 1 warp/node
    dim3 gemmGrid(D_HID / BN, N_CTAS);

    // Layer 1: (A_hat x) W1 + b1, relu       (agg1 = 4th launch -> ncu capture)
    k_agg_split<D_IN><<<aggBlocks, 256>>>(x, ah, al);
    k_gemm_mma<D_IN, true><<<gemmGrid, 256, SMEM_DYN>>>(ah, al,
        (__nv_bfloat16*)p1h, (__nv_bfloat16*)p1l, b1, h);

    // Layer 2
    k_agg_split<D_HID><<<aggBlocks, 256>>>(h, ah, al);
    k_gemm_mma<D_HID, true><<<gemmGrid, 256, SMEM_DYN>>>(ah, al,
        (__nv_bfloat16*)p2h, (__nv_bfloat16*)p2l, b2, h);

    // Layer 3 (no relu), straight to output
    k_agg_split<D_HID><<<aggBlocks, 256>>>(h, ah, al);
    k_gemm_mma<D_HID, false><<<gemmGrid, 256, SMEM_DYN>>>(ah, al,
        (__nv_bfloat16*)p3h, (__nv_bfloat16*)p3l, b3, out);
}

// round 14
// speedup vs baseline: 1.3052x; 1.3052x over previous
#include <cuda_runtime.h>
#include <cuda_bf16.h>
#include <cstdint>
#include <math.h>

#define N_NODES 50000
#define N_EDGES 500000
#define EN      (N_EDGES + N_NODES)   // 550000 incl. self loops
#define D_IN    128
#define D_HID   256
#define BM      128
#define BN      128
#define BK      64
#define N_CTAS  ((N_NODES + BM - 1) / BM)   // 391
#define M_PAD   (N_CTAS * BM)               // 50048

// ---------------- async-copy helpers (portable PTX, sm_80+) -----------------
__device__ __forceinline__ uint32_t smem_to_u32(const void* p) {
    uint32_t a;
    asm("{ .reg .u64 t; cvta.to.shared.u64 t, %1; cvt.u32.u64 %0, t; }" : "=r"(a) : "l"(p));
    return a;
}
__device__ __forceinline__ void cp_async16(uint32_t s, const void* g) {
    asm volatile("cp.async.cg.shared.global [%0], [%1], 16;" :: "r"(s), "l"(g));
}
__device__ __forceinline__ void cp_commit() {
    asm volatile("cp.async.commit_group;" ::: "memory");
}
template <int N>
__device__ __forceinline__ void cp_wait() {
    asm volatile("cp.async.wait_group %0;" :: "n"(N) : "memory");
}
__device__ __forceinline__ void ldsm_x4(uint32_t* r, uint32_t addr) {
    asm volatile("ldmatrix.sync.aligned.m8n8.x4.shared.b16 {%0,%1,%2,%3}, [%4];"
                 : "=r"(r[0]), "=r"(r[1]), "=r"(r[2]), "=r"(r[3]) : "r"(addr));
}
__device__ __forceinline__ void mma_bf16(float* c, const uint32_t* a, const uint32_t* b) {
    asm volatile(
        "mma.sync.aligned.m16n8k16.row.col.f32.bf16.bf16.f32 "
        "{%0,%1,%2,%3}, {%4,%5,%6,%7}, {%8,%9}, {%0,%1,%2,%3};"
        : "+f"(c[0]), "+f"(c[1]), "+f"(c[2]), "+f"(c[3])
        : "r"(a[0]), "r"(a[1]), "r"(a[2]), "r"(a[3]), "r"(b[0]), "r"(b[1]));
}

// ---------------- small float4 helpers (functions, not macros) --------------
__device__ __forceinline__ void fma4(float4& acc, float s, const float4& v) {
    acc.x = fmaf(s, v.x, acc.x); acc.y = fmaf(s, v.y, acc.y);
    acc.z = fmaf(s, v.z, acc.z); acc.w = fmaf(s, v.w, acc.w);
}
__device__ __forceinline__ void add4(float4& a, const float4& b) {
    a.x += b.x; a.y += b.y; a.z += b.z; a.w += b.w;
}

// ---------------- device scratch (static globals; no allocation) ------------
__device__ int   g_deg[N_NODES];          // zeroed each replay by k_scan
__device__ int   g_row_ptr[N_NODES + 1];
__device__ int   g_pos[N_NODES];
__device__ int   g_col[EN];
__device__ float g_enorm[EN];
__device__ float g_dinv[N_NODES];
__device__ __align__(16) float g_h[(size_t)N_NODES * D_HID];           // fp32 gemm outputs
__device__ __align__(16) __nv_bfloat16 g_xh[(size_t)M_PAD * D_IN];     // split-hi of x
__device__ __align__(16) __nv_bfloat16 g_xl[(size_t)M_PAD * D_IN];     // split-lo of x
__device__ __align__(16) __nv_bfloat16 g_ah[(size_t)M_PAD * D_HID];    // split-hi of agg out
__device__ __align__(16) __nv_bfloat16 g_al[(size_t)M_PAD * D_HID];    // split-lo of agg out
__device__ __align__(16) __nv_bfloat16 g_w1h[D_HID * D_IN];            // W^T [256,128]
__device__ __align__(16) __nv_bfloat16 g_w1l[D_HID * D_IN];
__device__ __align__(16) __nv_bfloat16 g_w2h[D_HID * D_HID];           // W^T [256,256]
__device__ __align__(16) __nv_bfloat16 g_w2l[D_HID * D_HID];
__device__ __align__(16) __nv_bfloat16 g_w3h[D_HID * D_HID];
__device__ __align__(16) __nv_bfloat16 g_w3l[D_HID * D_HID];

// ---------------- fused launch 1: degree count + W split + x split ----------
#define W1_ELEMS (D_IN * D_HID)
#define W23_ELEMS (D_HID * D_HID)
#define SPLIT_ELEMS (W1_ELEMS + 2 * W23_ELEMS)   // 163840
#define XSPLIT_THREADS ((N_NODES * D_IN) / 4)    // 1.6M (one float4 each)
#define L1_THREADS (N_EDGES + SPLIT_ELEMS + XSPLIT_THREADS)

__device__ __forceinline__ void split_one(const float* W, int K, int idx,
                                          __nv_bfloat16* oh, __nv_bfloat16* ol) {
    int k = idx / D_HID, n = idx % D_HID;
    float v = W[idx];
    __nv_bfloat16 h = __float2bfloat16(v);
    oh[(size_t)n * K + k] = h;
    ol[(size_t)n * K + k] = __float2bfloat16(v - __bfloat162float(h));
}

__global__ void k_count_split(const int* __restrict__ ei,
                              const float* __restrict__ W1,
                              const float* __restrict__ W2,
                              const float* __restrict__ W3,
                              const float* __restrict__ x) {
    int idx = blockIdx.x * blockDim.x + threadIdx.x;
    if (idx < N_EDGES) {
        atomicAdd(&g_deg[ei[N_EDGES + idx]], 1);
        return;
    }
    int j = idx - N_EDGES;
    if (j < W1_ELEMS) { split_one(W1, D_IN, j, g_w1h, g_w1l); return; }
    j -= W1_ELEMS;
    if (j < W23_ELEMS) { split_one(W2, D_HID, j, g_w2h, g_w2l); return; }
    j -= W23_ELEMS;
    if (j < W23_ELEMS) { split_one(W3, D_HID, j, g_w3h, g_w3l); return; }
    j -= W23_ELEMS;
    if (j < XSPLIT_THREADS) {
        float4 v = reinterpret_cast<const float4*>(x)[j];
        __nv_bfloat16 h0 = __float2bfloat16(v.x), h1 = __float2bfloat16(v.y);
        __nv_bfloat16 h2 = __float2bfloat16(v.z), h3 = __float2bfloat16(v.w);
        union { __nv_bfloat162 b[2]; uint2 u; } H, L;
        H.b[0] = __halves2bfloat162(h0, h1);
        H.b[1] = __halves2bfloat162(h2, h3);
        L.b[0] = __halves2bfloat162(__float2bfloat16(v.x - __bfloat162float(h0)),
                                    __float2bfloat16(v.y - __bfloat162float(h1)));
        L.b[1] = __halves2bfloat162(__float2bfloat16(v.z - __bfloat162float(h2)),
                                    __float2bfloat16(v.w - __bfloat162float(h3)));
        *reinterpret_cast<uint2*>(g_xh + (size_t)j * 4) = H.u;
        *reinterpret_cast<uint2*>(g_xl + (size_t)j * 4) = L.u;
    }
}

// Single-block scan. Degree = g_deg[i] + 1 (self loop). Zeroes g_deg after use.
__global__ void k_scan() {
    __shared__ int s[1024];
    const int t = threadIdx.x;
    const int CH = (N_NODES + 1023) / 1024;
    int start = t * CH;
    int end = start + CH; if (end > N_NODES) end = N_NODES;
    if (start > N_NODES) start = N_NODES;
    int sum = 0;
#pragma unroll 4
    for (int i = start; i < end; i++) sum += g_deg[i] + 1;
    s[t] = sum;
    __syncthreads();
    for (int off = 1; off < 1024; off <<= 1) {
        int v = (t >= off) ? s[t - off] : 0;
        __syncthreads();
        s[t] += v;
        __syncthreads();
    }
    int prefix = (t == 0) ? 0 : s[t - 1];
    for (int i = start; i < end; i++) {
        int d = g_deg[i] + 1;
        g_deg[i] = 0;
        g_row_ptr[i] = prefix;
        g_pos[i] = prefix;
        g_dinv[i] = rsqrtf((float)d);
        prefix += d;
    }
    if (t == 0) g_row_ptr[N_NODES] = s[1023];
}

__global__ void k_fill(const int* __restrict__ ei) {
    int idx = blockIdx.x * blockDim.x + threadIdx.x;
    if (idx < N_EDGES) {
        int s = ei[idx];
        int d = ei[N_EDGES + idx];
        int p = atomicAdd(&g_pos[d], 1);
        g_col[p] = s;
        g_enorm[p] = g_dinv[s] * g_dinv[d];
    } else if (idx < EN) {
        int i = idx - N_EDGES;
        int p = atomicAdd(&g_pos[i], 1);
        g_col[p] = i;
        float di = g_dinv[i];
        g_enorm[p] = di * di;
    }
}

// ---------------- aggregation (D=256) + bias/relu + split/fp32 out ----------
__device__ __forceinline__ void split_store4(__nv_bfloat16* oh, __nv_bfloat16* ol,
                                             size_t off, float4 a) {
    __nv_bfloat16 hx = __float2bfloat16(a.x);
    __nv_bfloat16 hy = __float2bfloat16(a.y);
    __nv_bfloat16 hz = __float2bfloat16(a.z);
    __nv_bfloat16 hw = __float2bfloat16(a.w);
    union { __nv_bfloat162 b[2]; uint2 u; } H, L;
    H.b[0] = __halves2bfloat162(hx, hy);
    H.b[1] = __halves2bfloat162(hz, hw);
    L.b[0] = __halves2bfloat162(__float2bfloat16(a.x - __bfloat162float(hx)),
                                __float2bfloat16(a.y - __bfloat162float(hy)));
    L.b[1] = __halves2bfloat162(__float2bfloat16(a.z - __bfloat162float(hz)),
                                __float2bfloat16(a.w - __bfloat162float(hw)));
    *reinterpret_cast<uint2*>(oh + off) = H.u;
    *reinterpret_cast<uint2*>(ol + off) = L.u;
}

// Warp per node; 4-way edge unroll with 4 independent accumulator sets
// (agg is MLP-latency bound; 4 concurrent gather chains). out = relu?(agg+b).
template <bool RELU, bool SPLIT>
__global__ __launch_bounds__(256) void k_agg(
        const float* __restrict__ feat, const float* __restrict__ bias,
        __nv_bfloat16* __restrict__ oh, __nv_bfloat16* __restrict__ ol,
        float* __restrict__ fo) {
    const int warp = blockIdx.x * (blockDim.x >> 5) + (threadIdx.x >> 5);
    const int lane = threadIdx.x & 31;
    if (warp >= N_NODES) return;
    const int rs = g_row_ptr[warp];
    const int re = g_row_ptr[warp + 1];
    const float4* f4 = reinterpret_cast<const float4*>(feat);

    float4 A0 = {0,0,0,0}, A1 = {0,0,0,0};
    float4 B0 = {0,0,0,0}, B1 = {0,0,0,0};
    float4 C0 = {0,0,0,0}, C1 = {0,0,0,0};
    float4 D0 = {0,0,0,0}, D1 = {0,0,0,0};

    for (int j = rs; j < re; j += 32) {
        int m = re - j; if (m > 32) m = 32;
        int c = 0; float w = 0.f;
        if (lane < m) { c = g_col[j + lane]; w = g_enorm[j + lane]; }
        int k = 0;
        for (; k + 4 <= m; k += 4) {
            int   c0 = __shfl_sync(0xffffffffu, c, k);
            float w0 = __shfl_sync(0xffffffffu, w, k);
            int   c1 = __shfl_sync(0xffffffffu, c, k + 1);
            float w1 = __shfl_sync(0xffffffffu, w, k + 1);
            int   c2 = __shfl_sync(0xffffffffu, c, k + 2);
            float w2 = __shfl_sync(0xffffffffu, w, k + 2);
            int   c3 = __shfl_sync(0xffffffffu, c, k + 3);
            float w3 = __shfl_sync(0xffffffffu, w, k + 3);
            const float4* r0 = f4 + (size_t)c0 * 64;
            const float4* r1 = f4 + (size_t)c1 * 64;
            const float4* r2 = f4 + (size_t)c2 * 64;
            const float4* r3 = f4 + (size_t)c3 * 64;
            float4 v0 = __ldg(r0 + lane),      v1 = __ldg(r1 + lane);
            float4 v2 = __ldg(r2 + lane),      v3 = __ldg(r3 + lane);
            float4 u0 = __ldg(r0 + 32 + lane), u1 = __ldg(r1 + 32 + lane);
            float4 u2 = __ldg(r2 + 32 + lane), u3 = __ldg(r3 + 32 + lane);
            fma4(A0, w0, v0); fma4(A1, w0, u0);
            fma4(B0, w1, v1); fma4(B1, w1, u1);
            fma4(C0, w2, v2); fma4(C1, w2, u2);
            fma4(D0, w3, v3); fma4(D1, w3, u3);
        }
        for (; k < m; ++k) {
            int   c0 = __shfl_sync(0xffffffffu, c, k);
            float w0 = __shfl_sync(0xffffffffu, w, k);
            const float4* r0 = f4 + (size_t)c0 * 64;
            float4 v0 = __ldg(r0 + lane);
            float4 u0 = __ldg(r0 + 32 + lane);
            fma4(A0, w0, v0); fma4(A1, w0, u0);
        }
    }
    add4(A0, B0); add4(C0, D0); add4(A0, C0);
    add4(A1, B1); add4(C1, D1); add4(A1, C1);

    const float4* b4 = reinterpret_cast<const float4*>(bias);
    float4 blo = __ldg(b4 + lane);
    float4 bhi = __ldg(b4 + 32 + lane);
    add4(A0, blo); add4(A1, bhi);
    if (RELU) {
        A0.x = fmaxf(A0.x, 0.f); A0.y = fmaxf(A0.y, 0.f);
        A0.z = fmaxf(A0.z, 0.f); A0.w = fmaxf(A0.w, 0.f);
        A1.x = fmaxf(A1.x, 0.f); A1.y = fmaxf(A1.y, 0.f);
        A1.z = fmaxf(A1.z, 0.f); A1.w = fmaxf(A1.w, 0.f);
    }
    if (SPLIT) {
        split_store4(oh, ol, (size_t)warp * D_HID + lane * 4, A0);
        split_store4(oh, ol, (size_t)warp * D_HID + 128 + lane * 4, A1);
    } else {
        float4* o4 = reinterpret_cast<float4*>(fo + (size_t)warp * D_HID);
        o4[lane] = A0;
        o4[32 + lane] = A1;
    }
}

// ---------------- split-bf16 mma.sync GEMM (R6-exact, no bias/relu) ---------
// C[M,256] = Ah@Bh^T + Ah@Bl^T + Al@Bh^T, B stored [N=256, K] bf16.
// CTA 256 thr, tile 128x128x64, double-buffered cp.async (2 x 32 KB dynamic
// SMEM, 2 CTAs/SM), SW128 swizzle, warps 4(M) x 2(N), warp tile 32x64.
#define STAGE_A 16384                     // 128 rows x 128 B
#define STAGE   32768                     // A + B per stage
#define SMEM_DYN (2 * STAGE)              // 65536

template <int KP>
__global__ __launch_bounds__(256, 2) void k_gemm_mma(
    const __nv_bfloat16* __restrict__ Ah, const __nv_bfloat16* __restrict__ Al,
    const __nv_bfloat16* __restrict__ Bh, const __nv_bfloat16* __restrict__ Bl,
    float* __restrict__ C) {
    extern __shared__ __align__(128) char smem[];
    const uint32_t sb = smem_to_u32(smem);
    const int tid  = threadIdx.x;
    const int wid  = tid >> 5;
    const int lane = tid & 31;
    const int wm   = wid >> 1;           // 0..3  (M)
    const int wn   = wid & 1;            // 0..1  (N)
    const int m0   = blockIdx.y * BM;
    const int n0   = blockIdx.x * BN;

    const __nv_bfloat16* Ap[3] = {Ah, Ah, Al};
    const __nv_bfloat16* Bp[3] = {Bh, Bl, Bh};
    constexpr int TP = KP / BK;          // tiles per part (2 or 4)
    constexpr int T  = 3 * TP;

    float acc[2][8][4];
#pragma unroll
    for (int i = 0; i < 2; i++)
#pragma unroll
        for (int j = 0; j < 8; j++)
#pragma unroll
            for (int q = 0; q < 4; q++) acc[i][j][q] = 0.f;

    auto load_tile = [&](int buf, int t) {
        const int part = t / TP;
        const int kc   = (t % TP) * BK;
        const __nv_bfloat16* Ag = Ap[part];
        const __nv_bfloat16* Bg = Bp[part];
        const uint32_t aB = sb + buf * STAGE;
        const uint32_t bB = aB + STAGE_A;
#pragma unroll
        for (int i = 0; i < 4; ++i) {
            int c   = tid + i * 256;           // 0..1023
            int row = c >> 3;
            int ch  = c & 7;
            uint32_t sw = (uint32_t)(ch ^ (row & 7)) << 4;
            cp_async16(aB + row * 128 + sw,
                       Ag + (size_t)(m0 + row) * KP + kc + ch * 8);
            cp_async16(bB + row * 128 + sw,
                       Bg + (size_t)(n0 + row) * KP + kc + ch * 8);
        }
    };

    load_tile(0, 0);
    cp_commit();

    for (int t = 0; t < T; ++t) {
        if (t + 1 < T) { load_tile((t + 1) & 1, t + 1); cp_commit(); cp_wait<1>(); }
        else           { cp_wait<0>(); }
        __syncthreads();

        const uint32_t aB = sb + (t & 1) * STAGE;
        const uint32_t bB = aB + STAGE_A;
#pragma unroll
        for (int ks = 0; ks < 4; ++ks) {
            uint32_t a[2][4];
#pragma unroll
            for (int mi = 0; mi < 2; ++mi) {
                int row = wm * 32 + mi * 16 + (lane & 15);
                uint32_t chunk = (uint32_t)((ks << 1) + (lane >> 4));
                uint32_t addr = aB + row * 128 + ((chunk ^ (row & 7)) << 4);
                ldsm_x4(a[mi], addr);
            }
            uint32_t b[8][2];
#pragma unroll
            for (int nj = 0; nj < 4; ++nj) {
                int g = lane >> 3;
                int nl = wn * 64 + nj * 16 + ((g >> 1) << 3) + (lane & 7);
                uint32_t chunk = (uint32_t)((ks << 1) + (g & 1));
                uint32_t addr = bB + nl * 128 + ((chunk ^ (nl & 7)) << 4);
                uint32_t r[4];
                ldsm_x4(r, addr);
                b[nj * 2 + 0][0] = r[0]; b[nj * 2 + 0][1] = r[1];
                b[nj * 2 + 1][0] = r[2]; b[nj * 2 + 1][1] = r[3];
            }
#pragma unroll
            for (int mi = 0; mi < 2; ++mi)
#pragma unroll
                for (int ni = 0; ni < 8; ++ni)
                    mma_bf16(acc[mi][ni], a[mi], b[ni]);
        }
        __syncthreads();
    }

    // epilogue: plain fp32 store (bias/relu live in the agg kernels now)
    const int lr = lane >> 2;
    const int lc = (lane & 3) * 2;
#pragma unroll
    for (int mi = 0; mi < 2; ++mi) {
        int rb = m0 + wm * 32 + mi * 16 + lr;
#pragma unroll
        for (int half = 0; half < 2; ++half) {
            int r = rb + half * 8;
            if (r < N_NODES) {
                float* crow = C + (size_t)r * D_HID;
#pragma unroll
                for (int ni = 0; ni < 8; ++ni) {
                    int col = n0 + wn * 64 + ni * 8 + lc;
                    float2 o;
                    o.x = acc[mi][ni][half * 2 + 0];
                    o.y = acc[mi][ni][half * 2 + 1];
                    *reinterpret_cast<float2*>(crow + col) = o;
                }
            }
        }
    }
}

// ---------------- launch ----------------------------------------------------
extern "C" void kernel_launch(void* const* d_in, const int* in_sizes, int n_in,
                              void* d_out, int out_size) {
    const float* x  = (const float*)d_in[0];
    const int*   ei = (const int*)  d_in[1];
    const float* W1 = (const float*)d_in[2];
    const float* b1 = (const float*)d_in[3];
    const float* W2 = (const float*)d_in[4];
    const float* b2 = (const float*)d_in[5];
    const float* W3 = (const float*)d_in[6];
    const float* b3 = (const float*)d_in[7];
    float* out = (float*)d_out;

    cudaFuncSetAttribute(k_gemm_mma<D_IN >, cudaFuncAttributeMaxDynamicSharedMemorySize, SMEM_DYN);
    cudaFuncSetAttribute(k_gemm_mma<D_HID>, cudaFuncAttributeMaxDynamicSharedMemorySize, SMEM_DYN);

    void *p_h, *p_xh, *p_xl, *p_ah, *p_al, *p1h, *p1l, *p2h, *p2l, *p3h, *p3l;
    cudaGetSymbolAddress(&p_h,  g_h);
    cudaGetSymbolAddress(&p_xh, g_xh);  cudaGetSymbolAddress(&p_xl, g_xl);
    cudaGetSymbolAddress(&p_ah, g_ah);  cudaGetSymbolAddress(&p_al, g_al);
    cudaGetSymbolAddress(&p1h, g_w1h);  cudaGetSymbolAddress(&p1l, g_w1l);
    cudaGetSymbolAddress(&p2h, g_w2h);  cudaGetSymbolAddress(&p2l, g_w2l);
    cudaGetSymbolAddress(&p3h, g_w3h);  cudaGetSymbolAddress(&p3l, g_w3l);
    float* h = (float*)p_h;
    __nv_bfloat16* xh = (__nv_bfloat16*)p_xh;
    __nv_bfloat16* xl = (__nv_bfloat16*)p_xl;
    __nv_bfloat16* ah = (__nv_bfloat16*)p_ah;
    __nv_bfloat16* al = (__nv_bfloat16*)p_al;

    // 1) degree count + W splits + x split   2) scan   3) fill
    k_count_split<<<(L1_THREADS + 255) / 256, 256>>>(ei, W1, W2, W3, x);
    k_scan<<<1, 1024>>>();
    k_fill<<<(EN + 255) / 256, 256>>>(ei);

    const int aggBlocks = (N_NODES + 7) / 8;   // 8 warps/block, 1 warp/node
    dim3 gemmGrid(D_HID / BN, N_CTAS);

    // Layer 1 (mult-first): y1 = x W1;  h1 = relu(A_hat y1 + b1)
    k_gemm_mma<D_IN><<<gemmGrid, 256, SMEM_DYN>>>(xh, xl,           // 4th launch -> ncu
        (__nv_bfloat16*)p1h, (__nv_bfloat16*)p1l, h);
    k_agg<true, true><<<aggBlocks, 256>>>(h, b1, ah, al, nullptr);

    // Layer 2: y2 = h1 W2;  h2 = relu(A_hat y2 + b2)
    k_gemm_mma<D_HID><<<gemmGrid, 256, SMEM_DYN>>>(ah, al,
        (__nv_bfloat16*)p2h, (__nv_bfloat16*)p2l, h);
    k_agg<true, true><<<aggBlocks, 256>>>(h, b2, ah, al, nullptr);

    // Layer 3: y3 = h2 W3;  out = A_hat y3 + b3 (no relu), fp32 direct
    k_gemm_mma<D_HID><<<gemmGrid, 256, SMEM_DYN>>>(ah, al,
        (__nv_bfloat16*)p3h, (__nv_bfloat16*)p3l, h);
    k_agg<false, false><<<aggBlocks, 256>>>(h, b3, nullptr, nullptr, out);
}